// round 15
// baseline (speedup 1.0000x reference)
#include <cuda_runtime.h>
#include <cuda_bf16.h>

// Output: 8192 x 8192 fp32, zeros except diag(triggers * mask).
//
// Pure-write fill at the HBM write-drain ceiling (~6.9 TB/s effective;
// confirmed across memset / STG.128 / STG.256 / st.wt / TMA-bulk — all
// converge). Byte-reduction schemes are structurally neutral-or-worse
// (eager dirty-line drain between replays, read rate == write rate at the
// LTS cap, no policy window, determinism rules ban cross-call state).
//
// This round covers the last unexplored axis: block size 512 (128 and 256
// already measured). Same optimal 2048 floats/warp, same one-shot grid,
// same v8 stores; 2048 CTAs x 512 threads = fewer CTA launch/retire events
// and a deeper per-SM eligible-warp pool at identical occupancy.

static constexpr int N = 8192;                 // row = 8192 floats = 32 KB
static constexpr int FLOATS_PER_WARP = 2048;   // quarter-row per warp
static constexpr int ITERS = 8;                // 8 x (32 lanes x 32B) = 2048 floats
static constexpr int TPB = 512;

__device__ __forceinline__ void stg256_zero(float* p) {
    asm volatile("st.global.v8.f32 [%0], {%1,%1,%1,%1,%1,%1,%1,%1};"
                 :: "l"(p), "f"(0.0f) : "memory");
}

__global__ void __launch_bounds__(TPB)
fill_diag_kernel(const float* __restrict__ triggers,
                 const int* __restrict__ mask,
                 float* __restrict__ out) {
    const unsigned tid  = blockIdx.x * TPB + threadIdx.x;
    const unsigned warp = tid >> 5;
    const unsigned lane = tid & 31;

    // This warp's region: floats [startf, startf + 2048) — within one row.
    const size_t startf = (size_t)warp * FLOATS_PER_WARP;
    float* base = out + startf + (size_t)lane * 8;

    // ---- Bulk zero-fill: each STG.256 is a contiguous 1KB warp wavefront ----
#pragma unroll
    for (int i = 0; i < ITERS; i++) {
        stg256_zero(base + (size_t)i * 256);
    }

    // ---- Diagonal fix-up ----
    // Warp region lies within one row (2048 | 8192). Row r's diagonal
    // element (col r) is in range iff d = r - c0 in [0, 2048). Owning lane
    // under the v8 layout is ((d>>3) & 31) — the same thread that zeroed
    // that address above, so program order gives the final value.
    const unsigned r  = (unsigned)(startf >> 13);   // row (N = 2^13)
    const unsigned c0 = (unsigned)(startf & (N - 1));
    const unsigned d  = r - c0;                     // wraps large if r < c0
    if (d < (unsigned)FLOATS_PER_WARP && ((d >> 3) & 31) == lane) {
        out[startf + d] = triggers[r] * (float)mask[r];
    }
}

extern "C" void kernel_launch(void* const* d_in, const int* in_sizes, int n_in,
                              void* d_out, int out_size) {
    const float* triggers = (const float*)d_in[0];
    const int*   mask     = (const int*)d_in[1];
    float*       out      = (float*)d_out;

    // 67,108,864 floats; 2048 per warp => 32768 warps => 2048 blocks of 512.
    const int blocks = (int)(((size_t)N * N / FLOATS_PER_WARP * 32) / TPB);
    fill_diag_kernel<<<blocks, TPB>>>(triggers, mask, out);
}

// round 16
// speedup vs baseline: 1.0054x; 1.0054x over previous
#include <cuda_runtime.h>
#include <cuda_bf16.h>

// Output: 8192 x 8192 fp32, zeros except diag(triggers * mask).
//
// FINAL — best-measured configuration (41.09-41.47us across reruns; the
// measured floor for this problem: 268MB mandatory writes / ~6.9 TB/s
// HBM3e write-drain + ~2.4us graph-replay overhead).
//
// Exhaustively measured over 15 rounds:
//  - store mechanisms (driver memset, STG.128, STG.256, st.global.wt,
//    TMA bulk): all converge at the same ~6.9 TB/s effective drain rate;
//  - byte-reduction schemes (evict_last/first hints, read-elision,
//    hot/stream L2 split): neutral or worse — dirty L2 lines drain eagerly
//    between replays, reads cost the same as writes at the LTS cap, no
//    policy window is available, determinism rules ban cross-call state;
//  - scheduling (grid shape, persistent grid, work/warp, block size):
//    one-shot 4096x256 with 2048 floats/warp is the optimum; all other
//    shapes equal or worse.
//
// Layout: each warp owns one quarter-row (2048 floats, 8KB contiguous);
// each STG.256 is a perfectly-coalesced 1KB warp wavefront. The diagonal
// element is overwritten AFTER the zero stores by the SAME thread that
// zeroed its address, so plain program order guarantees the final value —
// no sync, no extra kernel. Only 32 of 32768 warps touch the diagonal.

static constexpr int N = 8192;                 // row = 8192 floats = 32 KB
static constexpr int FLOATS_PER_WARP = 2048;   // quarter-row per warp
static constexpr int ITERS = 8;                // 8 x (32 lanes x 32B) = 2048 floats

__device__ __forceinline__ void stg256_zero(float* p) {
    asm volatile("st.global.v8.f32 [%0], {%1,%1,%1,%1,%1,%1,%1,%1};"
                 :: "l"(p), "f"(0.0f) : "memory");
}

__global__ void __launch_bounds__(256)
fill_diag_kernel(const float* __restrict__ triggers,
                 const int* __restrict__ mask,
                 float* __restrict__ out) {
    const unsigned tid  = blockIdx.x * blockDim.x + threadIdx.x;
    const unsigned warp = tid >> 5;
    const unsigned lane = tid & 31;

    // This warp's region: floats [startf, startf + 2048)
    const size_t startf = (size_t)warp * FLOATS_PER_WARP;
    float* base = out + startf + (size_t)lane * 8;

    // ---- Bulk zero-fill: each STG.256 is a contiguous 1KB warp wavefront ----
#pragma unroll
    for (int i = 0; i < ITERS; i++) {
        stg256_zero(base + (size_t)i * 256);
    }

    // ---- Diagonal fix-up ----
    // The warp's 2048 floats lie within one row (2048 | 8192). Row r's
    // diagonal element (column r) is in this warp's range iff d = r - c0
    // is in [0, 2048). The owning lane for float offset d under the v8
    // layout is ((d>>3) & 31) — exactly the thread that zeroed that
    // address above, so program order gives the final value.
    const unsigned r  = (unsigned)(startf >> 13);   // row (N = 2^13)
    const unsigned c0 = (unsigned)(startf & (N - 1));
    const unsigned d  = r - c0;                     // unsigned wrap => large if r < c0
    if (d < (unsigned)FLOATS_PER_WARP && ((d >> 3) & 31) == lane) {
        out[startf + d] = triggers[r] * (float)mask[r];
    }
}

extern "C" void kernel_launch(void* const* d_in, const int* in_sizes, int n_in,
                              void* d_out, int out_size) {
    const float* triggers = (const float*)d_in[0];
    const int*   mask     = (const int*)d_in[1];
    float*       out      = (float*)d_out;

    // Total floats = N*N = 67,108,864; 2048 per warp => 32768 warps
    // => 4096 blocks of 256 threads.
    const int blocks = (int)(((size_t)N * N / FLOATS_PER_WARP * 32) / 256);
    fill_diag_kernel<<<blocks, 256>>>(triggers, mask, out);
}